// round 8
// baseline (speedup 1.0000x reference)
#include <cuda_runtime.h>
#include <cuda_bf16.h>
#include <math.h>

// GCN_57449482551753: 2-layer GCN, sort-based aggregation (no feature atomics)
//   inputs: x[100000,128] f32, edge_index[2,1600000] (int64 OR int32, detected),
//           W1[128,128], b1[128], W2[128,16], b2[16]
//   output: concat(logits[100000,16], log_softmax[100000,16]) f32 (size-guarded)

#define NN 100000
#define FD 128
#define CD 16
#define SCAN_BLK 1024
#define N_SCAN_BLKS ((NN + SCAN_BLK - 1) / SCAN_BLK)   // 98
#define EMAX 1700000

// ---------------- device scratch (static, allocation-free) ----------------
__device__ __align__(16) float g_hs  [NN * FD];     // dinv*(x@W1)  (layer-1 msgs)
__device__ __align__(16) float g_gs  [NN * CD];     // dinv*(h2@W2) (layer-2 msgs)
__device__ float g_dinv[NN];
__device__ int   g_hist[NN];
__device__ int   g_row [NN + 1];
__device__ int   g_cur [NN];
__device__ int   g_bsum[N_SCAN_BLKS];
__device__ int   g_boff[N_SCAN_BLKS];
__device__ int   g_ssrc[EMAX];                      // src grouped by dst (CSR)
__device__ int   g_is64;

// ---------------- helpers ----------------
__device__ __forceinline__ int edge_at(const void* e, int i, int is64) {
    if (is64) return (int)(((const long long*)e)[i]);
    return ((const int*)e)[i];
}

// ---------------- kernels ----------------

// zero histogram + detect edge dtype
__global__ void k_init0(const void* eidx) {
    int i = blockIdx.x * blockDim.x + threadIdx.x;
    if (i < NN) g_hist[i] = 0;
    if (i == 0) {
        const int* p = (const int*)eidx;
        int all0 = 1;
        #pragma unroll
        for (int j = 0; j < 64; j++)
            if (p[2 * j + 1] != 0) all0 = 0;   // int64 hi-words are 0 for idx < 2^31
        g_is64 = all0;
    }
}

// histogram over dst
__global__ void k_hist(const void* __restrict__ eidx, int E) {
    int i = blockIdx.x * blockDim.x + threadIdx.x;
    if (i >= E) return;
    int d = edge_at(eidx, i + E, g_is64);
    atomicAdd(&g_hist[d], 1);
}

// block-level inclusive scan (Hillis-Steele), emits block-local exclusive + block sums
__global__ void k_scan1() {
    __shared__ int s[SCAN_BLK];
    int t = threadIdx.x;
    int i = blockIdx.x * SCAN_BLK + t;
    int v = (i < NN) ? g_hist[i] : 0;
    int x = v;
    s[t] = x;
    __syncthreads();
    #pragma unroll
    for (int o = 1; o < SCAN_BLK; o <<= 1) {
        int tmp = (t >= o) ? s[t - o] : 0;
        __syncthreads();
        x += tmp;
        s[t] = x;
        __syncthreads();
    }
    if (i < NN) g_row[i] = x - v;               // block-local exclusive
    if (t == SCAN_BLK - 1) g_bsum[blockIdx.x] = x;
}

// parallel scan of the 98 block sums (one 128-thread block)
__global__ void k_scan2() {
    __shared__ int s[128];
    int t = threadIdx.x;
    int orig = (t < N_SCAN_BLKS) ? g_bsum[t] : 0;
    int x = orig;
    s[t] = x;
    __syncthreads();
    #pragma unroll
    for (int o = 1; o < 128; o <<= 1) {
        int tmp = (t >= o) ? s[t - o] : 0;
        __syncthreads();
        x += tmp;
        s[t] = x;
        __syncthreads();
    }
    if (t < N_SCAN_BLKS) g_boff[t] = x - orig;  // exclusive
}

// finalize row offsets, cursors, dinv
__global__ void k_scan3(int E) {
    int i = blockIdx.x * blockDim.x + threadIdx.x;
    if (i < NN) {
        int rs = g_row[i] + g_boff[i >> 10];
        g_row[i] = rs;
        g_cur[i] = rs;
        g_dinv[i] = rsqrtf((float)(g_hist[i] + 1));   // +1 self loop
    } else if (i == NN) {
        g_row[NN] = E;
    }
}

// counting-sort scatter: src indices grouped by dst
__global__ void k_sort(const void* __restrict__ eidx, int E) {
    int i = blockIdx.x * blockDim.x + threadIdx.x;
    if (i >= E) return;
    int is64 = g_is64;
    int s = edge_at(eidx, i, is64);
    int d = edge_at(eidx, i + E, is64);
    int pos = atomicAdd(&g_cur[d], 1);
    g_ssrc[pos] = s;
}

// hs = dinv[row] * (x @ W1). 64-row tile, 256 threads, 8x4 register blocking.
__global__ void __launch_bounds__(256) k_gemm1(const float* __restrict__ x,
                                               const float* __restrict__ W1) {
    __shared__ float ws[32 * 128];  // [k][c] chunk, 16 KB
    __shared__ float xs[64 * 32];   // [r][k] chunk,  8 KB
    int t  = threadIdx.x;
    int tx = t & 31, ty = t >> 5;                  // tx -> 4 contiguous cols, ty -> 8 rows
    int row0 = blockIdx.x * 64;
    float acc[8][4] = {};

    for (int kb = 0; kb < 4; kb++) {
        const float4* Wsrc = (const float4*)(W1 + kb * 32 * 128);
        #pragma unroll
        for (int i = t; i < 1024; i += 256) ((float4*)ws)[i] = Wsrc[i];
        #pragma unroll
        for (int i = t; i < 512; i += 256) {
            int r = i >> 3, kk = i & 7;
            int gr = row0 + r; if (gr >= NN) gr = NN - 1;
            ((float4*)xs)[r * 8 + kk] =
                ((const float4*)(x + (size_t)gr * 128 + kb * 32))[kk];
        }
        __syncthreads();
        #pragma unroll 8
        for (int k = 0; k < 32; k++) {
            float4 wv = ((const float4*)ws)[k * 32 + tx];
            float xv[8];
            #pragma unroll
            for (int i = 0; i < 8; i++) xv[i] = xs[(ty * 8 + i) * 32 + k];  // broadcast
            #pragma unroll
            for (int i = 0; i < 8; i++) {
                acc[i][0] = fmaf(xv[i], wv.x, acc[i][0]);
                acc[i][1] = fmaf(xv[i], wv.y, acc[i][1]);
                acc[i][2] = fmaf(xv[i], wv.z, acc[i][2]);
                acc[i][3] = fmaf(xv[i], wv.w, acc[i][3]);
            }
        }
        __syncthreads();
    }
    #pragma unroll
    for (int i = 0; i < 8; i++) {
        int r = row0 + ty * 8 + i;
        if (r < NN) {
            float dv = g_dinv[r];
            float4 v;
            v.x = acc[i][0] * dv; v.y = acc[i][1] * dv;
            v.z = acc[i][2] * dv; v.w = acc[i][3] * dv;
            ((float4*)g_hs)[(size_t)r * 32 + tx] = v;
        }
    }
}

// layer-1 aggregation FUSED with layer-2 projection:
//   warp per dst node: CSR gather-accumulate in registers, self-loop + dinv +
//   bias + relu, then h2_row @ W2 in-warp (transposed W2 in smem, butterfly
//   reduce), writing only g_gs[node][0:16]. g_h2 never materialized.
__global__ void __launch_bounds__(256) k_agg1(const float* __restrict__ b1,
                                              const float* __restrict__ W2) {
    __shared__ float w2t[CD * FD];   // [c][k] transposed, 8 KB
    int t = threadIdx.x;
    for (int i = t; i < FD * CD; i += 256) {
        int c = i >> 7, k = i & 127;                // i = c*128+k
        w2t[i] = W2[k * 16 + c];
    }
    __syncthreads();

    int warp = (blockIdx.x * blockDim.x + t) >> 5;
    int lane = t & 31;
    if (warp >= NN) return;
    int beg = g_row[warp], end = g_row[warp + 1];
    const float4* hs4 = (const float4*)g_hs;
    float4 acc = hs4[(size_t)warp * 32 + lane];    // self loop
    int e = beg;
    for (; e + 4 <= end; e += 4) {
        int s0 = g_ssrc[e], s1 = g_ssrc[e + 1], s2 = g_ssrc[e + 2], s3 = g_ssrc[e + 3];
        float4 a = hs4[(size_t)s0 * 32 + lane];
        float4 b = hs4[(size_t)s1 * 32 + lane];
        float4 c = hs4[(size_t)s2 * 32 + lane];
        float4 d = hs4[(size_t)s3 * 32 + lane];
        acc.x += (a.x + b.x) + (c.x + d.x);
        acc.y += (a.y + b.y) + (c.y + d.y);
        acc.z += (a.z + b.z) + (c.z + d.z);
        acc.w += (a.w + b.w) + (c.w + d.w);
    }
    for (; e < end; e++) {
        int s = g_ssrc[e];
        float4 a = hs4[(size_t)s * 32 + lane];
        acc.x += a.x; acc.y += a.y; acc.z += a.z; acc.w += a.w;
    }
    float dv = g_dinv[warp];
    float4 bb = ((const float4*)b1)[lane];
    float4 h2;                                      // this lane's 4 h2 values (k = lane*4..+3)
    h2.x = fmaxf(fmaf(acc.x, dv, bb.x), 0.f);
    h2.y = fmaxf(fmaf(acc.y, dv, bb.y), 0.f);
    h2.z = fmaxf(fmaf(acc.z, dv, bb.z), 0.f);
    h2.w = fmaxf(fmaf(acc.w, dv, bb.w), 0.f);

    // p[c] = partial dot over this lane's 4 k's; LDS.128, conflict-free
    float p[16];
    const float4* w2t4 = (const float4*)w2t;
    #pragma unroll
    for (int c = 0; c < 16; c++) {
        float4 wv = w2t4[c * 32 + lane];
        p[c] = fmaf(h2.x, wv.x, fmaf(h2.y, wv.y, fmaf(h2.z, wv.z, h2.w * wv.w)));
    }
    // butterfly reduce all 16 sums across the warp
    #pragma unroll
    for (int o = 16; o; o >>= 1)
        #pragma unroll
        for (int c = 0; c < 16; c++)
            p[c] += __shfl_xor_sync(0xffffffffu, p[c], o);

    if (lane == 0) {
        float4* out4 = (float4*)(g_gs + (size_t)warp * 16);
        out4[0] = make_float4(p[0] * dv,  p[1] * dv,  p[2] * dv,  p[3] * dv);
        out4[1] = make_float4(p[4] * dv,  p[5] * dv,  p[6] * dv,  p[7] * dv);
        out4[2] = make_float4(p[8] * dv,  p[9] * dv,  p[10] * dv, p[11] * dv);
        out4[3] = make_float4(p[12] * dv, p[13] * dv, p[14] * dv, p[15] * dv);
    }
}

// layer-2 aggregation fused with bias + log_softmax + output write.
// Warp per node: lanes split into 2 halves of 16, each half strides edges by 2.
__global__ void k_agg2(const float* __restrict__ b2, float* __restrict__ out,
                       long long out_size) {
    int warp = (blockIdx.x * blockDim.x + threadIdx.x) >> 5;
    int lane = threadIdx.x & 31;
    if (warp >= NN) return;
    int c = lane & 15, half = lane >> 4;
    int beg = g_row[warp], end = g_row[warp + 1];
    float acc = half ? 0.f : g_gs[(size_t)warp * 16 + c];   // self loop in half 0
    for (int e = beg + half; e < end; e += 2)
        acc += g_gs[(size_t)g_ssrc[e] * 16 + c];
    acc += __shfl_xor_sync(0xffffffffu, acc, 16);           // merge halves

    float lg = fmaf(acc, g_dinv[warp], b2[c]);
    float mx = lg;
    #pragma unroll
    for (int o = 8; o; o >>= 1) mx = fmaxf(mx, __shfl_xor_sync(0xffffffffu, mx, o));
    float sum = expf(lg - mx);
    #pragma unroll
    for (int o = 8; o; o >>= 1) sum += __shfl_xor_sync(0xffffffffu, sum, o);
    float ls = lg - (logf(sum) + mx);

    if (half == 0) {
        long long base = (long long)warp * 16;
        if (base + 16 <= out_size) out[base + c] = lg;
        long long base2 = (long long)NN * 16 + base;
        if (base2 + 16 <= out_size) out[base2 + c] = ls;
    }
}

// ---------------- launch ----------------
extern "C" void kernel_launch(void* const* d_in, const int* in_sizes, int n_in,
                              void* d_out, int out_size) {
    const float* x   = (const float*)d_in[0];
    const void*  eix = d_in[1];                 // int64 or int32, detected on device
    const float* W1  = (const float*)d_in[2];
    const float* b1  = (const float*)d_in[3];
    const float* W2  = (const float*)d_in[4];
    const float* b2  = (const float*)d_in[5];
    float* out = (float*)d_out;

    int E = in_sizes[1] / 2;                    // 1,600,000

    k_init0<<<(NN + 255) / 256, 256>>>(eix);
    k_hist <<<(E + 255) / 256, 256>>>(eix, E);
    k_scan1<<<N_SCAN_BLKS, SCAN_BLK>>>();
    k_scan2<<<1, 128>>>();
    k_scan3<<<(NN + 1 + 255) / 256, 256>>>(E);
    k_sort <<<(E + 255) / 256, 256>>>(eix, E);
    k_gemm1<<<(NN + 63) / 64, 256>>>(x, W1);
    k_agg1 <<<(NN * 32 + 255) / 256, 256>>>(b1, W2);       // 12500 blocks
    k_agg2 <<<(NN * 32 + 255) / 256, 256>>>(b2, out, (long long)out_size);
}

// round 9
// speedup vs baseline: 1.0650x; 1.0650x over previous
#include <cuda_runtime.h>
#include <cuda_bf16.h>
#include <math.h>

// GCN_57449482551753: 2-layer GCN, sort-based aggregation (no feature atomics)
//   inputs: x[100000,128] f32, edge_index[2,1600000] (int64 OR int32, detected),
//           W1[128,128], b1[128], W2[128,16], b2[16]
//   output: concat(logits[100000,16], log_softmax[100000,16]) f32 (size-guarded)

#define NN 100000
#define FD 128
#define CD 16
#define SCAN_BLK 1024
#define N_SCAN_BLKS ((NN + SCAN_BLK - 1) / SCAN_BLK)   // 98
#define EMAX 1700000

// ---------------- device scratch (static, allocation-free) ----------------
__device__ __align__(16) float g_hs  [NN * FD];     // dinv*(x@W1)  (layer-1 msgs)
__device__ __align__(16) float g_gs  [NN * CD];     // dinv*(h2@W2) (layer-2 msgs)
__device__ float g_dinv[NN];
__device__ int   g_hist[NN];
__device__ int   g_row [NN + 1];
__device__ int   g_cur [NN];
__device__ int   g_bsum[N_SCAN_BLKS];
__device__ int   g_boff[N_SCAN_BLKS];
__device__ int   g_ssrc[EMAX];                      // src grouped by dst (CSR)
__device__ int   g_is64;

// ---------------- helpers ----------------
__device__ __forceinline__ int edge_at(const void* e, int i, int is64) {
    if (is64) return (int)(((const long long*)e)[i]);
    return ((const int*)e)[i];
}

// ---------------- kernels ----------------

// zero histogram + detect edge dtype
__global__ void k_init0(const void* eidx) {
    int i = blockIdx.x * blockDim.x + threadIdx.x;
    if (i < NN) g_hist[i] = 0;
    if (i == 0) {
        const int* p = (const int*)eidx;
        int all0 = 1;
        #pragma unroll
        for (int j = 0; j < 64; j++)
            if (p[2 * j + 1] != 0) all0 = 0;   // int64 hi-words are 0 for idx < 2^31
        g_is64 = all0;
    }
}

// histogram over dst
__global__ void k_hist(const void* __restrict__ eidx, int E) {
    int i = blockIdx.x * blockDim.x + threadIdx.x;
    if (i >= E) return;
    int d = edge_at(eidx, i + E, g_is64);
    atomicAdd(&g_hist[d], 1);
}

// block-level inclusive scan (Hillis-Steele), emits block-local exclusive + block sums
__global__ void k_scan1() {
    __shared__ int s[SCAN_BLK];
    int t = threadIdx.x;
    int i = blockIdx.x * SCAN_BLK + t;
    int v = (i < NN) ? g_hist[i] : 0;
    int x = v;
    s[t] = x;
    __syncthreads();
    #pragma unroll
    for (int o = 1; o < SCAN_BLK; o <<= 1) {
        int tmp = (t >= o) ? s[t - o] : 0;
        __syncthreads();
        x += tmp;
        s[t] = x;
        __syncthreads();
    }
    if (i < NN) g_row[i] = x - v;               // block-local exclusive
    if (t == SCAN_BLK - 1) g_bsum[blockIdx.x] = x;
}

// parallel scan of the 98 block sums (one 128-thread block)
__global__ void k_scan2() {
    __shared__ int s[128];
    int t = threadIdx.x;
    int orig = (t < N_SCAN_BLKS) ? g_bsum[t] : 0;
    int x = orig;
    s[t] = x;
    __syncthreads();
    #pragma unroll
    for (int o = 1; o < 128; o <<= 1) {
        int tmp = (t >= o) ? s[t - o] : 0;
        __syncthreads();
        x += tmp;
        s[t] = x;
        __syncthreads();
    }
    if (t < N_SCAN_BLKS) g_boff[t] = x - orig;  // exclusive
}

// finalize row offsets, cursors, dinv
__global__ void k_scan3(int E) {
    int i = blockIdx.x * blockDim.x + threadIdx.x;
    if (i < NN) {
        int rs = g_row[i] + g_boff[i >> 10];
        g_row[i] = rs;
        g_cur[i] = rs;
        g_dinv[i] = rsqrtf((float)(g_hist[i] + 1));   // +1 self loop
    } else if (i == NN) {
        g_row[NN] = E;
    }
}

// counting-sort scatter: src indices grouped by dst
__global__ void k_sort(const void* __restrict__ eidx, int E) {
    int i = blockIdx.x * blockDim.x + threadIdx.x;
    if (i >= E) return;
    int is64 = g_is64;
    int s = edge_at(eidx, i, is64);
    int d = edge_at(eidx, i + E, is64);
    int pos = atomicAdd(&g_cur[d], 1);
    g_ssrc[pos] = s;
}

// hs = dinv[row] * (x @ W1). 64-row tile, 256 threads, 8x4 register blocking.
__global__ void __launch_bounds__(256) k_gemm1(const float* __restrict__ x,
                                               const float* __restrict__ W1) {
    __shared__ float ws[32 * 128];  // [k][c] chunk, 16 KB
    __shared__ float xs[64 * 32];   // [r][k] chunk,  8 KB
    int t  = threadIdx.x;
    int tx = t & 31, ty = t >> 5;                  // tx -> 4 contiguous cols, ty -> 8 rows
    int row0 = blockIdx.x * 64;
    float acc[8][4] = {};

    for (int kb = 0; kb < 4; kb++) {
        const float4* Wsrc = (const float4*)(W1 + kb * 32 * 128);
        #pragma unroll
        for (int i = t; i < 1024; i += 256) ((float4*)ws)[i] = Wsrc[i];
        #pragma unroll
        for (int i = t; i < 512; i += 256) {
            int r = i >> 3, kk = i & 7;
            int gr = row0 + r; if (gr >= NN) gr = NN - 1;
            ((float4*)xs)[r * 8 + kk] =
                ((const float4*)(x + (size_t)gr * 128 + kb * 32))[kk];
        }
        __syncthreads();
        #pragma unroll 8
        for (int k = 0; k < 32; k++) {
            float4 wv = ((const float4*)ws)[k * 32 + tx];
            float xv[8];
            #pragma unroll
            for (int i = 0; i < 8; i++) xv[i] = xs[(ty * 8 + i) * 32 + k];  // broadcast
            #pragma unroll
            for (int i = 0; i < 8; i++) {
                acc[i][0] = fmaf(xv[i], wv.x, acc[i][0]);
                acc[i][1] = fmaf(xv[i], wv.y, acc[i][1]);
                acc[i][2] = fmaf(xv[i], wv.z, acc[i][2]);
                acc[i][3] = fmaf(xv[i], wv.w, acc[i][3]);
            }
        }
        __syncthreads();
    }
    #pragma unroll
    for (int i = 0; i < 8; i++) {
        int r = row0 + ty * 8 + i;
        if (r < NN) {
            float dv = g_dinv[r];
            float4 v;
            v.x = acc[i][0] * dv; v.y = acc[i][1] * dv;
            v.z = acc[i][2] * dv; v.w = acc[i][3] * dv;
            ((float4*)g_hs)[(size_t)r * 32 + tx] = v;
        }
    }
}

// layer-1 aggregation FUSED with layer-2 projection:
//   warp per dst node: CSR gather-accumulate in registers, self-loop + dinv +
//   bias + relu, then h2_row @ W2 in-warp. Reduction of the 32x16 partials is
//   a DISTRIBUTED TREE (16 SHFLs/warp, not 80): each round halves the values
//   per lane; final 16 sums land distributed across even lanes.
__global__ void __launch_bounds__(256) k_agg1(const float* __restrict__ b1,
                                              const float* __restrict__ W2) {
    __shared__ float w2t[CD * FD];   // [c][k] transposed, 8 KB
    int t = threadIdx.x;
    for (int i = t; i < FD * CD; i += 256) {
        int c = i >> 7, k = i & 127;                // i = c*128+k
        w2t[i] = W2[k * 16 + c];
    }
    __syncthreads();

    int warp = (blockIdx.x * blockDim.x + t) >> 5;
    int lane = t & 31;
    if (warp >= NN) return;
    int beg = g_row[warp], end = g_row[warp + 1];
    const float4* hs4 = (const float4*)g_hs;
    float4 acc = hs4[(size_t)warp * 32 + lane];    // self loop
    int e = beg;
    for (; e + 4 <= end; e += 4) {
        int s0 = g_ssrc[e], s1 = g_ssrc[e + 1], s2 = g_ssrc[e + 2], s3 = g_ssrc[e + 3];
        float4 a = hs4[(size_t)s0 * 32 + lane];
        float4 b = hs4[(size_t)s1 * 32 + lane];
        float4 c = hs4[(size_t)s2 * 32 + lane];
        float4 d = hs4[(size_t)s3 * 32 + lane];
        acc.x += (a.x + b.x) + (c.x + d.x);
        acc.y += (a.y + b.y) + (c.y + d.y);
        acc.z += (a.z + b.z) + (c.z + d.z);
        acc.w += (a.w + b.w) + (c.w + d.w);
    }
    for (; e < end; e++) {
        int s = g_ssrc[e];
        float4 a = hs4[(size_t)s * 32 + lane];
        acc.x += a.x; acc.y += a.y; acc.z += a.z; acc.w += a.w;
    }
    float dv = g_dinv[warp];
    float4 bb = ((const float4*)b1)[lane];
    float4 h2;                                      // this lane's 4 h2 values (k = lane*4..+3)
    h2.x = fmaxf(fmaf(acc.x, dv, bb.x), 0.f);
    h2.y = fmaxf(fmaf(acc.y, dv, bb.y), 0.f);
    h2.z = fmaxf(fmaf(acc.z, dv, bb.z), 0.f);
    h2.w = fmaxf(fmaf(acc.w, dv, bb.w), 0.f);

    // p[c] = partial dot over this lane's 4 k's; LDS.128, conflict-free
    float p[16];
    const float4* w2t4 = (const float4*)w2t;
    #pragma unroll
    for (int c = 0; c < 16; c++) {
        float4 wv = w2t4[c * 32 + lane];
        p[c] = fmaf(h2.x, wv.x, fmaf(h2.y, wv.y, fmaf(h2.z, wv.z, h2.w * wv.w)));
    }

    // Distributed tree reduction: 32 lanes x 16 vals -> 16 sums across lanes.
    // Round (o, n): side = lane&o; keep v[i] (side 0) or v[i+n/2] (side 1),
    // exchange the other half. After all rounds lane L (even) owns
    // c = 8*bit4(L) + 4*bit3(L) + 2*bit2(L) + bit1(L).
    unsigned FULL = 0xffffffffu;
    float q8[8];
    {
        int side = (lane >> 4) & 1;
        #pragma unroll
        for (int i = 0; i < 8; i++) {
            float keep = side ? p[i + 8] : p[i];
            float send = side ? p[i] : p[i + 8];
            q8[i] = keep + __shfl_xor_sync(FULL, send, 16);
        }
    }
    float q4[4];
    {
        int side = (lane >> 3) & 1;
        #pragma unroll
        for (int i = 0; i < 4; i++) {
            float keep = side ? q8[i + 4] : q8[i];
            float send = side ? q8[i] : q8[i + 4];
            q4[i] = keep + __shfl_xor_sync(FULL, send, 8);
        }
    }
    float q2[2];
    {
        int side = (lane >> 2) & 1;
        #pragma unroll
        for (int i = 0; i < 2; i++) {
            float keep = side ? q2[0] : q2[0];  // placeholder overwritten below
            (void)keep;
            float k2 = side ? q4[i + 2] : q4[i];
            float s2 = side ? q4[i] : q4[i + 2];
            q2[i] = k2 + __shfl_xor_sync(FULL, s2, 4);
        }
    }
    float q1;
    {
        int side = (lane >> 1) & 1;
        float k1 = side ? q2[1] : q2[0];
        float s1 = side ? q2[0] : q2[1];
        q1 = k1 + __shfl_xor_sync(FULL, s1, 2);
    }
    q1 += __shfl_xor_sync(FULL, q1, 1);             // merge bit0 pairs

    if ((lane & 1) == 0) {
        int c = (((lane >> 4) & 1) << 3) | (((lane >> 3) & 1) << 2) |
                (((lane >> 2) & 1) << 1) | ((lane >> 1) & 1);
        g_gs[(size_t)warp * 16 + c] = q1 * dv;
    }
}

// layer-2 aggregation fused with bias + log_softmax + output write.
// Warp per node: lanes split into 2 halves of 16, each half strides edges by 2.
__global__ void k_agg2(const float* __restrict__ b2, float* __restrict__ out,
                       long long out_size) {
    int warp = (blockIdx.x * blockDim.x + threadIdx.x) >> 5;
    int lane = threadIdx.x & 31;
    if (warp >= NN) return;
    int c = lane & 15, half = lane >> 4;
    int beg = g_row[warp], end = g_row[warp + 1];
    float acc = half ? 0.f : g_gs[(size_t)warp * 16 + c];   // self loop in half 0
    for (int e = beg + half; e < end; e += 2)
        acc += g_gs[(size_t)g_ssrc[e] * 16 + c];
    acc += __shfl_xor_sync(0xffffffffu, acc, 16);           // merge halves

    float lg = fmaf(acc, g_dinv[warp], b2[c]);
    float mx = lg;
    #pragma unroll
    for (int o = 8; o; o >>= 1) mx = fmaxf(mx, __shfl_xor_sync(0xffffffffu, mx, o));
    float sum = expf(lg - mx);
    #pragma unroll
    for (int o = 8; o; o >>= 1) sum += __shfl_xor_sync(0xffffffffu, sum, o);
    float ls = lg - (logf(sum) + mx);

    if (half == 0) {
        long long base = (long long)warp * 16;
        if (base + 16 <= out_size) out[base + c] = lg;
        long long base2 = (long long)NN * 16 + base;
        if (base2 + 16 <= out_size) out[base2 + c] = ls;
    }
}

// ---------------- launch ----------------
extern "C" void kernel_launch(void* const* d_in, const int* in_sizes, int n_in,
                              void* d_out, int out_size) {
    const float* x   = (const float*)d_in[0];
    const void*  eix = d_in[1];                 // int64 or int32, detected on device
    const float* W1  = (const float*)d_in[2];
    const float* b1  = (const float*)d_in[3];
    const float* W2  = (const float*)d_in[4];
    const float* b2  = (const float*)d_in[5];
    float* out = (float*)d_out;

    int E = in_sizes[1] / 2;                    // 1,600,000

    k_init0<<<(NN + 255) / 256, 256>>>(eix);
    k_hist <<<(E + 255) / 256, 256>>>(eix, E);
    k_scan1<<<N_SCAN_BLKS, SCAN_BLK>>>();
    k_scan2<<<1, 128>>>();
    k_scan3<<<(NN + 1 + 255) / 256, 256>>>(E);
    k_sort <<<(E + 255) / 256, 256>>>(eix, E);
    k_gemm1<<<(NN + 63) / 64, 256>>>(x, W1);
    k_agg1 <<<(NN * 32 + 255) / 256, 256>>>(b1, W2);       // 12500 blocks
    k_agg2 <<<(NN * 32 + 255) / 256, 256>>>(b2, out, (long long)out_size);
}

// round 12
// speedup vs baseline: 1.0731x; 1.0076x over previous
#include <cuda_runtime.h>
#include <cuda_bf16.h>
#include <cuda_fp16.h>
#include <math.h>

// GCN_57449482551753: 2-layer GCN, sort-based aggregation (no feature atomics)
//   inputs: x[100000,128] f32, edge_index[2,1600000] (int64 OR int32, detected),
//           W1[128,128], b1[128], W2[128,16], b2[16]
//   output: concat(logits[100000,16], log_softmax[100000,16]) f32 (size-guarded)
// Layer-1 messages stored in fp16 (halves the dominant L2 gather traffic).

#define NN 100000
#define FD 128
#define CD 16
#define SCAN_BLK 1024
#define N_SCAN_BLKS ((NN + SCAN_BLK - 1) / SCAN_BLK)   // 98
#define EMAX 1700000

// ---------------- device scratch (static, allocation-free) ----------------
__device__ __align__(16) __half g_hs [NN * FD];     // fp16 dinv*(x@W1) (layer-1 msgs)
__device__ __align__(16) float  g_gs [NN * CD];     // dinv*(h2@W2) (layer-2 msgs)
__device__ float g_dinv[NN];
__device__ int   g_hist[NN];
__device__ int   g_row [NN + 1];
__device__ int   g_cur [NN];
__device__ int   g_bsum[N_SCAN_BLKS];
__device__ int   g_boff[N_SCAN_BLKS];
__device__ int   g_ssrc[EMAX];                      // src grouped by dst (CSR)
__device__ int   g_is64;

// ---------------- helpers ----------------
__device__ __forceinline__ int edge_at(const void* e, int i, int is64) {
    if (is64) return (int)(((const long long*)e)[i]);
    return ((const int*)e)[i];
}

// unpack uint2 (4 fp16) -> 4 floats, accumulate into float4
__device__ __forceinline__ void acc_h4(float4& acc, uint2 v) {
    __half2 h0 = *reinterpret_cast<__half2*>(&v.x);
    __half2 h1 = *reinterpret_cast<__half2*>(&v.y);
    float2 f0 = __half22float2(h0);
    float2 f1 = __half22float2(h1);
    acc.x += f0.x; acc.y += f0.y; acc.z += f1.x; acc.w += f1.y;
}

// ---------------- kernels ----------------

// zero histogram + detect edge dtype
__global__ void k_init0(const void* eidx) {
    int i = blockIdx.x * blockDim.x + threadIdx.x;
    if (i < NN) g_hist[i] = 0;
    if (i == 0) {
        const int* p = (const int*)eidx;
        int all0 = 1;
        #pragma unroll
        for (int j = 0; j < 64; j++)
            if (p[2 * j + 1] != 0) all0 = 0;   // int64 hi-words are 0 for idx < 2^31
        g_is64 = all0;
    }
}

// histogram over dst
__global__ void k_hist(const void* __restrict__ eidx, int E) {
    int i = blockIdx.x * blockDim.x + threadIdx.x;
    if (i >= E) return;
    int d = edge_at(eidx, i + E, g_is64);
    atomicAdd(&g_hist[d], 1);
}

// block-level inclusive scan (Hillis-Steele), emits block-local exclusive + block sums
__global__ void k_scan1() {
    __shared__ int s[SCAN_BLK];
    int t = threadIdx.x;
    int i = blockIdx.x * SCAN_BLK + t;
    int v = (i < NN) ? g_hist[i] : 0;
    int x = v;
    s[t] = x;
    __syncthreads();
    #pragma unroll
    for (int o = 1; o < SCAN_BLK; o <<= 1) {
        int tmp = (t >= o) ? s[t - o] : 0;
        __syncthreads();
        x += tmp;
        s[t] = x;
        __syncthreads();
    }
    if (i < NN) g_row[i] = x - v;               // block-local exclusive
    if (t == SCAN_BLK - 1) g_bsum[blockIdx.x] = x;
}

// parallel scan of the 98 block sums (one 128-thread block)
__global__ void k_scan2() {
    __shared__ int s[128];
    int t = threadIdx.x;
    int orig = (t < N_SCAN_BLKS) ? g_bsum[t] : 0;
    int x = orig;
    s[t] = x;
    __syncthreads();
    #pragma unroll
    for (int o = 1; o < 128; o <<= 1) {
        int tmp = (t >= o) ? s[t - o] : 0;
        __syncthreads();
        x += tmp;
        s[t] = x;
        __syncthreads();
    }
    if (t < N_SCAN_BLKS) g_boff[t] = x - orig;  // exclusive
}

// finalize row offsets, cursors, dinv
__global__ void k_scan3(int E) {
    int i = blockIdx.x * blockDim.x + threadIdx.x;
    if (i < NN) {
        int rs = g_row[i] + g_boff[i >> 10];
        g_row[i] = rs;
        g_cur[i] = rs;
        g_dinv[i] = rsqrtf((float)(g_hist[i] + 1));   // +1 self loop
    } else if (i == NN) {
        g_row[NN] = E;
    }
}

// counting-sort scatter: src indices grouped by dst
__global__ void k_sort(const void* __restrict__ eidx, int E) {
    int i = blockIdx.x * blockDim.x + threadIdx.x;
    if (i >= E) return;
    int is64 = g_is64;
    int s = edge_at(eidx, i, is64);
    int d = edge_at(eidx, i + E, is64);
    int pos = atomicAdd(&g_cur[d], 1);
    g_ssrc[pos] = s;
}

// hs = fp16( dinv[row] * (x @ W1) ). 64-row tile, 256 threads, 8x4 blocking.
__global__ void __launch_bounds__(256) k_gemm1(const float* __restrict__ x,
                                               const float* __restrict__ W1) {
    __shared__ float ws[32 * 128];  // [k][c] chunk, 16 KB
    __shared__ float xs[64 * 32];   // [r][k] chunk,  8 KB
    int t  = threadIdx.x;
    int tx = t & 31, ty = t >> 5;                  // tx -> 4 contiguous cols, ty -> 8 rows
    int row0 = blockIdx.x * 64;
    float acc[8][4] = {};

    for (int kb = 0; kb < 4; kb++) {
        const float4* Wsrc = (const float4*)(W1 + kb * 32 * 128);
        #pragma unroll
        for (int i = t; i < 1024; i += 256) ((float4*)ws)[i] = Wsrc[i];
        #pragma unroll
        for (int i = t; i < 512; i += 256) {
            int r = i >> 3, kk = i & 7;
            int gr = row0 + r; if (gr >= NN) gr = NN - 1;
            ((float4*)xs)[r * 8 + kk] =
                ((const float4*)(x + (size_t)gr * 128 + kb * 32))[kk];
        }
        __syncthreads();
        #pragma unroll 8
        for (int k = 0; k < 32; k++) {
            float4 wv = ((const float4*)ws)[k * 32 + tx];
            float xv[8];
            #pragma unroll
            for (int i = 0; i < 8; i++) xv[i] = xs[(ty * 8 + i) * 32 + k];  // broadcast
            #pragma unroll
            for (int i = 0; i < 8; i++) {
                acc[i][0] = fmaf(xv[i], wv.x, acc[i][0]);
                acc[i][1] = fmaf(xv[i], wv.y, acc[i][1]);
                acc[i][2] = fmaf(xv[i], wv.z, acc[i][2]);
                acc[i][3] = fmaf(xv[i], wv.w, acc[i][3]);
            }
        }
        __syncthreads();
    }
    #pragma unroll
    for (int i = 0; i < 8; i++) {
        int r = row0 + ty * 8 + i;
        if (r < NN) {
            float dv = g_dinv[r];
            __half2 lo = __float22half2_rn(make_float2(acc[i][0] * dv, acc[i][1] * dv));
            __half2 hi = __float22half2_rn(make_float2(acc[i][2] * dv, acc[i][3] * dv));
            uint2 pv;
            pv.x = *reinterpret_cast<unsigned*>(&lo);
            pv.y = *reinterpret_cast<unsigned*>(&hi);
            ((uint2*)g_hs)[(size_t)r * 32 + tx] = pv;
        }
    }
}

// layer-1 aggregation FUSED with layer-2 projection:
//   warp per dst node: CSR gather fp16 messages (256 B rows), accumulate fp32,
//   self-loop + dinv + bias + relu, then h2_row @ W2 in-warp via distributed
//   tree reduction (16 SHFLs/warp); writes g_gs[node][0:16].
__global__ void __launch_bounds__(256) k_agg1(const float* __restrict__ b1,
                                              const float* __restrict__ W2) {
    __shared__ float w2t[CD * FD];   // [c][k] transposed, 8 KB
    int t = threadIdx.x;
    for (int i = t; i < FD * CD; i += 256) {
        int c = i >> 7, k = i & 127;                // i = c*128+k
        w2t[i] = W2[k * 16 + c];
    }
    __syncthreads();

    int warp = (blockIdx.x * blockDim.x + t) >> 5;
    int lane = t & 31;
    if (warp >= NN) return;
    int beg = g_row[warp], end = g_row[warp + 1];
    const uint2* hs2 = (const uint2*)g_hs;          // 4 fp16 per lane per row
    float4 acc = make_float4(0.f, 0.f, 0.f, 0.f);
    acc_h4(acc, hs2[(size_t)warp * 32 + lane]);     // self loop
    int e = beg;
    for (; e + 4 <= end; e += 4) {
        int s0 = g_ssrc[e], s1 = g_ssrc[e + 1], s2 = g_ssrc[e + 2], s3 = g_ssrc[e + 3];
        uint2 v0 = hs2[(size_t)s0 * 32 + lane];
        uint2 v1 = hs2[(size_t)s1 * 32 + lane];
        uint2 v2 = hs2[(size_t)s2 * 32 + lane];
        uint2 v3 = hs2[(size_t)s3 * 32 + lane];
        acc_h4(acc, v0); acc_h4(acc, v1); acc_h4(acc, v2); acc_h4(acc, v3);
    }
    for (; e < end; e++) {
        acc_h4(acc, hs2[(size_t)g_ssrc[e] * 32 + lane]);
    }
    float dv = g_dinv[warp];
    float4 bb = ((const float4*)b1)[lane];
    float4 h2;                                      // this lane's 4 h2 values (k = lane*4..+3)
    h2.x = fmaxf(fmaf(acc.x, dv, bb.x), 0.f);
    h2.y = fmaxf(fmaf(acc.y, dv, bb.y), 0.f);
    h2.z = fmaxf(fmaf(acc.z, dv, bb.z), 0.f);
    h2.w = fmaxf(fmaf(acc.w, dv, bb.w), 0.f);

    // p[c] = partial dot over this lane's 4 k's; LDS.128, conflict-free
    float p[16];
    const float4* w2t4 = (const float4*)w2t;
    #pragma unroll
    for (int c = 0; c < 16; c++) {
        float4 wv = w2t4[c * 32 + lane];
        p[c] = fmaf(h2.x, wv.x, fmaf(h2.y, wv.y, fmaf(h2.z, wv.z, h2.w * wv.w)));
    }

    // Distributed tree reduction: 32 lanes x 16 vals -> 16 sums across lanes.
    unsigned FULL = 0xffffffffu;
    float q8[8];
    {
        int side = (lane >> 4) & 1;
        #pragma unroll
        for (int i = 0; i < 8; i++) {
            float keep = side ? p[i + 8] : p[i];
            float send = side ? p[i] : p[i + 8];
            q8[i] = keep + __shfl_xor_sync(FULL, send, 16);
        }
    }
    float q4[4];
    {
        int side = (lane >> 3) & 1;
        #pragma unroll
        for (int i = 0; i < 4; i++) {
            float keep = side ? q8[i + 4] : q8[i];
            float send = side ? q8[i] : q8[i + 4];
            q4[i] = keep + __shfl_xor_sync(FULL, send, 8);
        }
    }
    float q2[2];
    {
        int side = (lane >> 2) & 1;
        #pragma unroll
        for (int i = 0; i < 2; i++) {
            float keep = side ? q4[i + 2] : q4[i];
            float send = side ? q4[i] : q4[i + 2];
            q2[i] = keep + __shfl_xor_sync(FULL, send, 4);
        }
    }
    float q1;
    {
        int side = (lane >> 1) & 1;
        float keep = side ? q2[1] : q2[0];
        float send = side ? q2[0] : q2[1];
        q1 = keep + __shfl_xor_sync(FULL, send, 2);
    }
    q1 += __shfl_xor_sync(FULL, q1, 1);             // merge bit0 pairs

    if ((lane & 1) == 0) {
        int c = (((lane >> 4) & 1) << 3) | (((lane >> 3) & 1) << 2) |
                (((lane >> 2) & 1) << 1) | ((lane >> 1) & 1);
        g_gs[(size_t)warp * 16 + c] = q1 * dv;
    }
}

// layer-2 aggregation fused with bias + log_softmax + output write.
// Warp per node: lanes split into 2 halves of 16, each half strides edges by 2.
__global__ void k_agg2(const float* __restrict__ b2, float* __restrict__ out,
                       long long out_size) {
    int warp = (blockIdx.x * blockDim.x + threadIdx.x) >> 5;
    int lane = threadIdx.x & 31;
    if (warp >= NN) return;
    int c = lane & 15, half = lane >> 4;
    int beg = g_row[warp], end = g_row[warp + 1];
    float acc = half ? 0.f : g_gs[(size_t)warp * 16 + c];   // self loop in half 0
    for (int e = beg + half; e < end; e += 2)
        acc += g_gs[(size_t)g_ssrc[e] * 16 + c];
    acc += __shfl_xor_sync(0xffffffffu, acc, 16);           // merge halves

    float lg = fmaf(acc, g_dinv[warp], b2[c]);
    float mx = lg;
    #pragma unroll
    for (int o = 8; o; o >>= 1) mx = fmaxf(mx, __shfl_xor_sync(0xffffffffu, mx, o));
    float sum = expf(lg - mx);
    #pragma unroll
    for (int o = 8; o; o >>= 1) sum += __shfl_xor_sync(0xffffffffu, sum, o);
    float ls = lg - (logf(sum) + mx);

    if (half == 0) {
        long long base = (long long)warp * 16;
        if (base + 16 <= out_size) out[base + c] = lg;
        long long base2 = (long long)NN * 16 + base;
        if (base2 + 16 <= out_size) out[base2 + c] = ls;
    }
}

// ---------------- launch ----------------
extern "C" void kernel_launch(void* const* d_in, const int* in_sizes, int n_in,
                              void* d_out, int out_size) {
    const float* x   = (const float*)d_in[0];
    const void*  eix = d_in[1];                 // int64 or int32, detected on device
    const float* W1  = (const float*)d_in[2];
    const float* b1  = (const float*)d_in[3];
    const float* W2  = (const float*)d_in[4];
    const float* b2  = (const float*)d_in[5];
    float* out = (float*)d_out;

    int E = in_sizes[1] / 2;                    // 1,600,000

    k_init0<<<(NN + 255) / 256, 256>>>(eix);
    k_hist <<<(E + 255) / 256, 256>>>(eix, E);
    k_scan1<<<N_SCAN_BLKS, SCAN_BLK>>>();
    k_scan2<<<1, 128>>>();
    k_scan3<<<(NN + 1 + 255) / 256, 256>>>(E);
    k_sort <<<(E + 255) / 256, 256>>>(eix, E);
    k_gemm1<<<(NN + 63) / 64, 256>>>(x, W1);
    k_agg1 <<<(NN * 32 + 255) / 256, 256>>>(b1, W2);       // 12500 blocks
    k_agg2 <<<(NN * 32 + 255) / 256, 256>>>(b2, out, (long long)out_size);
}